// round 14
// baseline (speedup 1.0000x reference)
#include <cuda_runtime.h>
#include <cuda_fp16.h>
#include <cstdint>

// ---------------------------------------------------------------------------
// EncoderBlock: pre-norm transformer block.
// GEMMs + flash attention via mma.sync m16n8k16 fp16 (fp32 accumulate).
// Large GEMMs: 256x128 CTA tile (16 warps) to raise the crossbar ceiling.
// FA: FA2 register-P. QKV epilogue writes V transposed. Merged setup kernel.
// B=2, S=2048, D=1024, H=16, DK=64, DFF=4096
// ---------------------------------------------------------------------------

namespace {
constexpr int B_ = 2, S_ = 2048, D_ = 1024, H_ = 16, DK_ = 64, DFF_ = 4096;
constexpr int ROWS_ = B_ * S_;            // 4096
constexpr int QKV_LD = 3 * D_;            // 3072
constexpr float EPS_ = 1e-6f;
constexpr float SFT_SC = 0.125f * 1.44269504088896f;   // (1/8)*log2(e)
}

// Scratch (allocation-free: __device__ globals)
__device__ __align__(16) __half g_ln[ROWS_ * D_];
__device__ __align__(16) __half g_qkv[ROWS_ * QKV_LD];
__device__ __align__(16) __half g_vT[B_ * H_ * DK_ * S_];
__device__ __align__(16) __half g_attn[ROWS_ * D_];
__device__ __align__(16) float  g_x2[ROWS_ * D_];
__device__ __align__(16) __half g_hbuf[ROWS_ * DFF_];
__device__ __align__(16) __half g_wr[12 * 1024 * 1024];   // half weights (24MB)
__device__ __align__(16) float  g_bqkv[QKV_LD];

// ---------------------------------------------------------------------------
// PTX helpers
// ---------------------------------------------------------------------------
__device__ __forceinline__ uint32_t smem_u32(const void* p) {
    uint32_t a;
    asm("{ .reg .u64 t; cvta.to.shared.u64 t, %1; cvt.u32.u64 %0, t; }"
        : "=r"(a) : "l"(p));
    return a;
}

__device__ __forceinline__ void cp_async16(uint32_t s, const void* g) {
    asm volatile("cp.async.cg.shared.global [%0], [%1], 16;" :: "r"(s), "l"(g));
}
#define CP_COMMIT() asm volatile("cp.async.commit_group;" ::: "memory")
#define CP_WAIT(n)  asm volatile("cp.async.wait_group %0;" :: "n"(n) : "memory")

__device__ __forceinline__ void mma_f16(float* c, const uint32_t* a, const uint32_t* b) {
    asm volatile(
        "mma.sync.aligned.m16n8k16.row.col.f32.f16.f16.f32 "
        "{%0,%1,%2,%3}, {%4,%5,%6,%7}, {%8,%9}, {%0,%1,%2,%3};"
        : "+f"(c[0]), "+f"(c[1]), "+f"(c[2]), "+f"(c[3])
        : "r"(a[0]), "r"(a[1]), "r"(a[2]), "r"(a[3]), "r"(b[0]), "r"(b[1]));
}

__device__ __forceinline__ void ldsm_x4(uint32_t* r, uint32_t saddr) {
    asm volatile("ldmatrix.sync.aligned.m8n8.x4.shared.b16 {%0,%1,%2,%3}, [%4];"
                 : "=r"(r[0]), "=r"(r[1]), "=r"(r[2]), "=r"(r[3]) : "r"(saddr));
}

__device__ __forceinline__ uint32_t h2u(__half2 h) {
    return *reinterpret_cast<uint32_t*>(&h);
}

// ---------------------------------------------------------------------------
// Fused setup: weight fp32->fp16 + bias concat + LN1, one launch (1D grid).
// ---------------------------------------------------------------------------
__global__ void setup_kernel(const float* __restrict__ wq, const float* __restrict__ wk,
                             const float* __restrict__ wv, const float* __restrict__ wo,
                             const float* __restrict__ w1, const float* __restrict__ w2,
                             const float* __restrict__ bq, const float* __restrict__ bk,
                             const float* __restrict__ bv,
                             __half* __restrict__ dst, float* __restrict__ bqkv,
                             const float* __restrict__ x, __half* __restrict__ ln,
                             const float* __restrict__ alpha,
                             const float* __restrict__ beta) {
    __shared__ float red_s[256];
    __shared__ float red_q[256];
    constexpr int M1 = 1024 * 1024;
    const int bid = blockIdx.x;
    const int tid = threadIdx.x;

    if (bid < 12288) {                      // weight conversion
        const float* src;
        size_t off;
        int rb;
        if (bid < 1024)      { src = wq; off = 0;              rb = bid; }
        else if (bid < 2048) { src = wk; off = (size_t)M1;     rb = bid - 1024; }
        else if (bid < 3072) { src = wv; off = 2 * (size_t)M1; rb = bid - 2048; }
        else if (bid < 4096) { src = wo; off = 3 * (size_t)M1; rb = bid - 3072; }
        else if (bid < 8192) { src = w1; off = 4 * (size_t)M1; rb = bid - 4096; }
        else                 { src = w2; off = 8 * (size_t)M1; rb = bid - 8192; }
        const int i = rb * 256 + tid;
        float4 v = reinterpret_cast<const float4*>(src)[i];
        __half2* d = reinterpret_cast<__half2*>(dst + off) + i * 2;
        d[0] = __floats2half2_rn(v.x, v.y);
        d[1] = __floats2half2_rn(v.z, v.w);
        return;
    }
    if (bid < 12300) {                      // bias concat
        const int i = (bid - 12288) * 256 + tid;
        if (i < 1024) bqkv[i] = bq[i];
        else if (i < 2048) bqkv[i] = bk[i - 1024];
        else bqkv[i] = bv[i - 2048];
        return;
    }
    // LN1: one block per row
    const int row = bid - 12300;
    const size_t off = (size_t)row * D_;
    float4 r = reinterpret_cast<const float4*>(x + off)[tid];
    float s = r.x + r.y + r.z + r.w;
    float q = r.x * r.x + r.y * r.y + r.z * r.z + r.w * r.w;
    red_s[tid] = s;
    red_q[tid] = q;
    __syncthreads();
    #pragma unroll
    for (int st = 128; st > 0; st >>= 1) {
        if (tid < st) { red_s[tid] += red_s[tid + st]; red_q[tid] += red_q[tid + st]; }
        __syncthreads();
    }
    const float mean = red_s[0] * (1.0f / D_);
    float var = (red_q[0] - (float)D_ * mean * mean) * (1.0f / (float)(D_ - 1));
    var = fmaxf(var, 0.0f);
    const float sc = alpha[0] / (sqrtf(var) + EPS_);
    const float sh = beta[0];
    __half2* yo = reinterpret_cast<__half2*>(ln + off) + tid * 2;
    yo[0] = __floats2half2_rn((r.x - mean) * sc + sh, (r.y - mean) * sc + sh);
    yo[1] = __floats2half2_rn((r.z - mean) * sc + sh, (r.w - mean) * sc + sh);
}

// ---------------------------------------------------------------------------
// LayerNorm (exact fp32 math): unbiased std (ddof=1), scalar alpha/beta.
// ---------------------------------------------------------------------------
__global__ void layernorm_kernel(const float* __restrict__ x, __half* __restrict__ y,
                                 const float* __restrict__ alpha,
                                 const float* __restrict__ beta) {
    __shared__ float red_s[256];
    __shared__ float red_q[256];
    const int tid = threadIdx.x;
    const size_t off = (size_t)blockIdx.x * D_;
    float4 r = reinterpret_cast<const float4*>(x + off)[tid];
    float s = r.x + r.y + r.z + r.w;
    float q = r.x * r.x + r.y * r.y + r.z * r.z + r.w * r.w;
    red_s[tid] = s;
    red_q[tid] = q;
    __syncthreads();
    #pragma unroll
    for (int st = 128; st > 0; st >>= 1) {
        if (tid < st) { red_s[tid] += red_s[tid + st]; red_q[tid] += red_q[tid + st]; }
        __syncthreads();
    }
    const float mean = red_s[0] * (1.0f / D_);
    float var = (red_q[0] - (float)D_ * mean * mean) * (1.0f / (float)(D_ - 1));
    var = fmaxf(var, 0.0f);
    const float sc = alpha[0] / (sqrtf(var) + EPS_);
    const float sh = beta[0];
    __half2* yo = reinterpret_cast<__half2*>(y + off) + tid * 2;
    yo[0] = __floats2half2_rn((r.x - mean) * sc + sh, (r.y - mean) * sc + sh);
    yo[1] = __floats2half2_rn((r.z - mean) * sc + sh, (r.w - mean) * sc + sh);
}

// ---------------------------------------------------------------------------
// fp16 tensor-core GEMM (NT): BM x 128 x 64 CTA tile, warp tile 64x32,
// BM*2 threads (BM=128: 8 warps, 2 CTAs/SM; BM=256: 16 warps, 1 CTA/SM).
// VTRANS: blocks with blockIdx.x >= 16 write their tile transposed to vt.
// ---------------------------------------------------------------------------
template <int BM, bool RELU, bool OUTHALF, bool VTRANS, int MAXB>
__global__ void __launch_bounds__(BM * 2, MAXB)
mma_gemm(const __half* __restrict__ A, const __half* __restrict__ Bm,
         const float* __restrict__ bias, const float* __restrict__ res,
         void* __restrict__ Cv, __half* __restrict__ vt,
         int K, int lda, int ldb, int ldc, float scale) {
    constexpr int THREADS = BM * 2;
    constexpr int STGB = (BM + 128) * 128;   // bytes per stage
    constexpr int BOFFB = BM * 128;          // B region offset (bytes)
    constexpr int ALD = BM * 8 / THREADS;    // = 4
    constexpr int BLD = 128 * 8 / THREADS;   // 4 (BM=128) or 2 (BM=256)

    extern __shared__ char smc[];

    const int tid = threadIdx.x;
    const int wid = tid >> 5;
    const int lane = tid & 31;
    const int grp = lane >> 2;
    const int tid4 = lane & 3;
    const int wm0 = (wid >> 2) * 64;         // BM=128: 0..64; BM=256: 0..192
    const int wn0 = (wid & 3) * 32;

    const int l7 = lane & 7;
    const int aRB = ((lane >> 3) & 1) * 8 + l7;
    const int aCB = lane >> 4;
    const int bRB = ((lane >> 4) & 1) * 8 + l7;
    const int bCB = (lane >> 3) & 1;

    const int row0 = blockIdx.y * BM;
    const int col0 = blockIdx.x * 128;

    int aGo[ALD]; uint32_t aSm[ALD];
    #pragma unroll
    for (int l = 0; l < ALD; l++) {
        const int idx4 = tid + l * THREADS;
        const int r = idx4 >> 3, ch = idx4 & 7;
        aGo[l] = (row0 + r) * lda + ch * 8;
        aSm[l] = (uint32_t)(r * 128 + ((ch ^ (r & 7)) << 4));
    }
    int bGo[BLD]; uint32_t bSm[BLD];
    #pragma unroll
    for (int l = 0; l < BLD; l++) {
        const int idx4 = tid + l * THREADS;
        const int r = idx4 >> 3, ch = idx4 & 7;
        bGo[l] = (col0 + r) * ldb + ch * 8;
        bSm[l] = (uint32_t)(BOFFB + r * 128 + ((ch ^ (r & 7)) << 4));
    }
    const uint32_t smBase = smem_u32(smc);

    float acc[4][4][4];
    #pragma unroll
    for (int i = 0; i < 4; i++)
        #pragma unroll
        for (int j = 0; j < 4; j++)
            #pragma unroll
            for (int e = 0; e < 4; e++) acc[i][j][e] = 0.0f;

    const int nch = K / 64;

    #pragma unroll
    for (int s = 0; s < 2; s++) {
        const uint32_t sb = smBase + (uint32_t)(s % 3) * STGB;
        const int k0 = s * 64;
        #pragma unroll
        for (int l = 0; l < ALD; l++) cp_async16(sb + aSm[l], A + aGo[l] + k0);
        #pragma unroll
        for (int l = 0; l < BLD; l++) cp_async16(sb + bSm[l], Bm + bGo[l] + k0);
        CP_COMMIT();
    }

    for (int ci = 0; ci < nch; ci++) {
        if (ci + 2 < nch) { CP_WAIT(1); } else { CP_WAIT(0); }
        __syncthreads();
        if (ci + 2 < nch) {
            const int s = ci + 2;
            const uint32_t sb = smBase + (uint32_t)(s % 3) * STGB;
            const int k0 = s * 64;
            #pragma unroll
            for (int l = 0; l < ALD; l++) cp_async16(sb + aSm[l], A + aGo[l] + k0);
            #pragma unroll
            for (int l = 0; l < BLD; l++) cp_async16(sb + bSm[l], Bm + bGo[l] + k0);
            CP_COMMIT();
        }

        const uint32_t suA = smBase + (uint32_t)(ci % 3) * STGB;
        const uint32_t suB = suA + (uint32_t)BOFFB;

        #pragma unroll
        for (int ks = 0; ks < 4; ks++) {
            const uint32_t aSw = (uint32_t)(((2 * ks + aCB) ^ l7) << 4);
            const uint32_t bSw = (uint32_t)(((2 * ks + bCB) ^ l7) << 4);
            uint32_t a[4][4];
            #pragma unroll
            for (int ma = 0; ma < 4; ma++)
                ldsm_x4(a[ma], suA + (uint32_t)(wm0 + ma * 16 + aRB) * 128u + aSw);
            uint32_t bq[2][4];
            #pragma unroll
            for (int np = 0; np < 2; np++)
                ldsm_x4(bq[np], suB + (uint32_t)(wn0 + np * 16 + bRB) * 128u + bSw);
            #pragma unroll
            for (int ma = 0; ma < 4; ma++)
                #pragma unroll
                for (int na = 0; na < 4; na++)
                    mma_f16(acc[ma][na], a[ma], &bq[na >> 1][(na & 1) * 2]);
        }
    }

    if (VTRANS && blockIdx.x >= 16) {
        // transposed epilogue: stage sT[feature][s-row], write vT rows coalesced
        constexpr int TP = BM + 8;
        __half* sT = reinterpret_cast<__half*>(smc);
        __syncthreads();
        #pragma unroll
        for (int ma = 0; ma < 4; ma++) {
            const int rr = wm0 + ma * 16 + grp;
            #pragma unroll
            for (int na = 0; na < 4; na++) {
                const int cc = wn0 + na * 8 + tid4 * 2;
                float2 v0, v1;
                v0.x = acc[ma][na][0]; v0.y = acc[ma][na][1];
                v1.x = acc[ma][na][2]; v1.y = acc[ma][na][3];
                if (bias) {
                    const float2 bv = *reinterpret_cast<const float2*>(bias + col0 + cc);
                    v0.x += bv.x; v0.y += bv.y; v1.x += bv.x; v1.y += bv.y;
                }
                sT[cc * TP + rr]           = __float2half_rn(v0.x);
                sT[(cc + 1) * TP + rr]     = __float2half_rn(v0.y);
                sT[cc * TP + rr + 8]       = __float2half_rn(v1.x);
                sT[(cc + 1) * TP + rr + 8] = __float2half_rn(v1.y);
            }
        }
        __syncthreads();
        const int b = row0 >> 11;
        const int s0 = row0 & 2047;
        constexpr int GPC = BM / 8;           // 8-row groups per column
        #pragma unroll
        for (int l = 0; l < 8; l++) {
            const int idx = tid + l * THREADS;
            const int c = idx / GPC, su = idx % GPC;
            const int f = col0 - 2048 + c;
            const int h = f >> 6, n = f & 63;
            const uint4 val = *reinterpret_cast<const uint4*>(&sT[c * TP + su * 8]);
            *reinterpret_cast<uint4*>(
                vt + ((size_t)((b * 16 + h) * 64 + n)) * 2048 + s0 + su * 8) = val;
        }
        return;
    }

    #pragma unroll
    for (int ma = 0; ma < 4; ma++) {
        const int rr = row0 + wm0 + ma * 16 + grp;
        #pragma unroll
        for (int na = 0; na < 4; na++) {
            const int cc = col0 + wn0 + na * 8 + tid4 * 2;
            float2 v0, v1;
            v0.x = acc[ma][na][0] * scale; v0.y = acc[ma][na][1] * scale;
            v1.x = acc[ma][na][2] * scale; v1.y = acc[ma][na][3] * scale;
            if (bias) {
                const float2 bv = *reinterpret_cast<const float2*>(bias + cc);
                v0.x += bv.x; v0.y += bv.y; v1.x += bv.x; v1.y += bv.y;
            }
            if (RELU) {
                v0.x = fmaxf(v0.x, 0.0f); v0.y = fmaxf(v0.y, 0.0f);
                v1.x = fmaxf(v1.x, 0.0f); v1.y = fmaxf(v1.y, 0.0f);
            }
            const long long o0 = (long long)rr * ldc + cc;
            const long long o1 = (long long)(rr + 8) * ldc + cc;
            if (OUTHALF) {
                __half* C = reinterpret_cast<__half*>(Cv);
                *reinterpret_cast<__half2*>(C + o0) = __floats2half2_rn(v0.x, v0.y);
                *reinterpret_cast<__half2*>(C + o1) = __floats2half2_rn(v1.x, v1.y);
            } else {
                float* C = reinterpret_cast<float*>(Cv);
                if (res) {
                    const float2 r0 = *reinterpret_cast<const float2*>(res + o0);
                    const float2 r1 = *reinterpret_cast<const float2*>(res + o1);
                    v0.x += r0.x; v0.y += r0.y; v1.x += r1.x; v1.y += r1.y;
                }
                *reinterpret_cast<float2*>(C + o0) = v0;
                *reinterpret_cast<float2*>(C + o1) = v1;
            }
        }
    }
}

// ---------------------------------------------------------------------------
// Fused flash attention, FA2 register-P (proven R12 config).
// ---------------------------------------------------------------------------
namespace fa {
constexpr int oQ = 0, oK = 16384, oVT = 49152;
constexpr int SMEM_BYTES = 81920;
constexpr int NIT = S_ / 128;                  // 16
}

__global__ void __launch_bounds__(256, 2)
flash_attn_kernel(const __half* __restrict__ q, const __half* __restrict__ k,
                  const __half* __restrict__ vT, const int* __restrict__ mask,
                  __half* __restrict__ attn) {
    using namespace fa;
    extern __shared__ char smc[];
    const uint32_t smb = smem_u32(smc);

    const int tid = threadIdx.x, wid = tid >> 5, lane = tid & 31;
    const int grp = lane >> 2, tid4 = lane & 3;
    const int wm = wid * 16;

    const int l7 = lane & 7;
    const int aRB = ((lane >> 3) & 1) * 8 + l7;
    const int aCB = lane >> 4;
    const int bRB = ((lane >> 4) & 1) * 8 + l7;
    const int bCB = (lane >> 3) & 1;

    const int qt = blockIdx.x;
    const int bh = blockIdx.y;
    const int b = bh >> 4, hh = bh & 15;
    const int q0 = qt * 128;
    const __half* Qg = q + ((size_t)(b * S_ + q0)) * QKV_LD + hh * 64;
    const __half* Kg = k + ((size_t)(b * S_)) * QKV_LD + hh * 64;
    const __half* Vg = vT + (size_t)bh * 64 * S_;
    const int* maskb = mask + b * S_;

    #pragma unroll
    for (int l = 0; l < 4; l++) {
        const int i4 = tid + l * 256;
        const int r = i4 >> 3, c = i4 & 7;
        cp_async16(smb + (uint32_t)(oQ + r * 128 + ((c ^ (r & 7)) << 4)),
                   Qg + (size_t)r * QKV_LD + c * 8);
    }
    #pragma unroll
    for (int l = 0; l < 4; l++) {
        const int i4 = tid + l * 256;
        const int r = i4 >> 3, c = i4 & 7;
        cp_async16(smb + (uint32_t)(oK + r * 128 + ((c ^ (r & 7)) << 4)),
                   Kg + (size_t)r * QKV_LD + c * 8);
    }
    CP_COMMIT();
    #pragma unroll
    for (int l = 0; l < 4; l++) {
        const int i4 = tid + l * 256;
        const int r = i4 >> 4, c = i4 & 15;
        cp_async16(smb + (uint32_t)(oVT + r * 256 + ((c ^ (r & 7)) << 4)),
                   Vg + (size_t)r * S_ + c * 8);
    }
    CP_COMMIT();

    float acc_o[8][4];
    #pragma unroll
    for (int j = 0; j < 8; j++)
        #pragma unroll
        for (int e = 0; e < 4; e++) acc_o[j][e] = 0.0f;

    float m0 = -3.0e38f, m1 = -3.0e38f;
    float l0 = 0.0f, l1 = 0.0f;

    for (int it = 0; it < NIT; ++it) {
        const int kv0 = it * 128;
        const uint32_t kCur = smb + (uint32_t)(oK + (it & 1) * 16384);
        const uint32_t vCur = smb + (uint32_t)(oVT + (it & 1) * 16384);

        CP_WAIT(1);
        __syncthreads();            // barrier 1

        if (it + 1 < NIT) {
            const uint32_t kNxt = smb + (uint32_t)(oK + ((it + 1) & 1) * 16384);
            const __half* Kn = Kg + (size_t)(kv0 + 128) * QKV_LD;
            #pragma unroll
            for (int l = 0; l < 4; l++) {
                const int i4 = tid + l * 256;
                const int r = i4 >> 3, c = i4 & 7;
                cp_async16(kNxt + (uint32_t)(r * 128 + ((c ^ (r & 7)) << 4)),
                           Kn + (size_t)r * QKV_LD + c * 8);
            }
            CP_COMMIT();
        }

        // ---- S = Q K^T : warp = 16 rows x 128 kv ----
        float acc_s[16][4];
        #pragma unroll
        for (int j = 0; j < 16; j++)
            #pragma unroll
            for (int e = 0; e < 4; e++) acc_s[j][e] = 0.0f;

        #pragma unroll
        for (int ks = 0; ks < 4; ks++) {
            const uint32_t aSw = (uint32_t)(((2 * ks + aCB) ^ l7) << 4);
            const uint32_t bSw = (uint32_t)(((2 * ks + bCB) ^ l7) << 4);
            uint32_t a[4];
            ldsm_x4(a, smb + (uint32_t)(oQ + (wm + aRB) * 128) + aSw);
            #pragma unroll
            for (int h = 0; h < 2; h++) {
                uint32_t bq[4][4];
                #pragma unroll
                for (int np = 0; np < 4; np++)
                    ldsm_x4(bq[np],
                            kCur + (uint32_t)((h * 64 + np * 16 + bRB) * 128) + bSw);
                #pragma unroll
                for (int j = 0; j < 8; j++)
                    mma_f16(acc_s[h * 8 + j], a, &bq[j >> 1][(j & 1) * 2]);
            }
        }

        // ---- mask + log2 scale + in-warp row max ----
        float p0 = -3.0e38f, p1 = -3.0e38f;
        #pragma unroll
        for (int na = 0; na < 16; na++) {
            const int cg = kv0 + na * 8 + tid4 * 2;
            const int2 mm = *reinterpret_cast<const int2*>(maskb + cg);
            float* s = acc_s[na];
            s[0] = mm.x ? s[0] * SFT_SC : -1e9f;
            s[1] = mm.y ? s[1] * SFT_SC : -1e9f;
            s[2] = mm.x ? s[2] * SFT_SC : -1e9f;
            s[3] = mm.y ? s[3] * SFT_SC : -1e9f;
            p0 = fmaxf(p0, fmaxf(s[0], s[1]));
            p1 = fmaxf(p1, fmaxf(s[2], s[3]));
        }
        #pragma unroll
        for (int d2 = 1; d2 < 4; d2 <<= 1) {
            p0 = fmaxf(p0, __shfl_xor_sync(0xffffffffu, p0, d2));
            p1 = fmaxf(p1, __shfl_xor_sync(0xffffffffu, p1, d2));
        }
        const float mn0 = fmaxf(m0, p0);
        const float mn1 = fmaxf(m1, p1);
        const float c0 = exp2f(m0 - mn0);
        const float c1 = exp2f(m1 - mn1);
        m0 = mn0; m1 = mn1;

        // ---- exp2, convert P to half2 register fragments, row sums ----
        uint32_t phl[16], phh[16];
        float s0sum = 0.0f, s1sum = 0.0f;
        #pragma unroll
        for (int na = 0; na < 16; na++) {
            float* s = acc_s[na];
            s[0] = exp2f(s[0] - mn0);
            s[1] = exp2f(s[1] - mn0);
            s[2] = exp2f(s[2] - mn1);
            s[3] = exp2f(s[3] - mn1);
            s0sum += s[0] + s[1];
            s1sum += s[2] + s[3];
            phl[na] = h2u(__floats2half2_rn(s[0], s[1]));
            phh[na] = h2u(__floats2half2_rn(s[2], s[3]));
        }
        #pragma unroll
        for (int d2 = 1; d2 < 4; d2 <<= 1) {
            s0sum += __shfl_xor_sync(0xffffffffu, s0sum, d2);
            s1sum += __shfl_xor_sync(0xffffffffu, s1sum, d2);
        }
        l0 = l0 * c0 + s0sum;
        l1 = l1 * c1 + s1sum;

        CP_WAIT(1);
        __syncthreads();            // barrier 2: VT visible

        if (it + 1 < NIT) {
            const uint32_t vNxt = smb + (uint32_t)(oVT + ((it + 1) & 1) * 16384);
            const __half* Vn = Vg + kv0 + 128;
            #pragma unroll
            for (int l = 0; l < 4; l++) {
                const int i4 = tid + l * 256;
                const int r = i4 >> 4, c = i4 & 15;
                cp_async16(vNxt + (uint32_t)(r * 256 + ((c ^ (r & 7)) << 4)),
                           Vn + (size_t)r * S_ + c * 8);
            }
            CP_COMMIT();
        }

        // ---- correction + PV ----
        #pragma unroll
        for (int na = 0; na < 8; na++) {
            acc_o[na][0] *= c0; acc_o[na][1] *= c0;
            acc_o[na][2] *= c1; acc_o[na][3] *= c1;
        }
        #pragma unroll
        for (int ks = 0; ks < 8; ks++) {
            uint32_t a[4] = { phl[2 * ks], phh[2 * ks], phl[2 * ks + 1], phh[2 * ks + 1] };
            const uint32_t bSw = (uint32_t)(((2 * ks + bCB) ^ l7) << 4);
            uint32_t bq[4][4];
            #pragma unroll
            for (int np = 0; np < 4; np++)
                ldsm_x4(bq[np], vCur + (uint32_t)((np * 16 + bRB) * 256) + bSw);
            #pragma unroll
            for (int nd = 0; nd < 8; nd++)
                mma_f16(acc_o[nd], a, &bq[nd >> 1][(nd & 1) * 2]);
        }
    }

    // ---- normalize and store ----
    const float inv0 = 1.0f / l0;
    const float inv1 = 1.0f / l1;
    const int rA = wm + grp;
    #pragma unroll
    for (int nd = 0; nd < 8; nd++) {
        const int cd = nd * 8 + tid4 * 2;
        const size_t o0 = ((size_t)(b * S_ + q0 + rA)) * D_ + hh * 64 + cd;
        const size_t o1 = o0 + (size_t)8 * D_;
        *reinterpret_cast<__half2*>(attn + o0) =
            __floats2half2_rn(acc_o[nd][0] * inv0, acc_o[nd][1] * inv0);
        *reinterpret_cast<__half2*>(attn + o1) =
            __floats2half2_rn(acc_o[nd][2] * inv1, acc_o[nd][3] * inv1);
    }
}

// ---------------------------------------------------------------------------
// kernel_launch
// ---------------------------------------------------------------------------
extern "C" void kernel_launch(void* const* d_in, const int* in_sizes, int n_in,
                              void* d_out, int out_size) {
    const float* x    = (const float*)d_in[0];
    const int*   msk  = (const int*)  d_in[1];
    const float* wq   = (const float*)d_in[2];
    const float* bq   = (const float*)d_in[3];
    const float* wk   = (const float*)d_in[4];
    const float* bk_  = (const float*)d_in[5];
    const float* wv   = (const float*)d_in[6];
    const float* bv   = (const float*)d_in[7];
    const float* wo   = (const float*)d_in[8];
    const float* bo   = (const float*)d_in[9];
    const float* w1   = (const float*)d_in[10];
    const float* b1   = (const float*)d_in[11];
    const float* w2   = (const float*)d_in[12];
    const float* b2   = (const float*)d_in[13];
    const float* a1   = (const float*)d_in[14];
    const float* be1  = (const float*)d_in[15];
    const float* a2   = (const float*)d_in[16];
    const float* be2  = (const float*)d_in[17];
    float* out = (float*)d_out;

    __half *ln, *qkv, *vT, *attn, *hb, *wr;
    float *x2, *bqkv;
    cudaGetSymbolAddress((void**)&ln,   g_ln);
    cudaGetSymbolAddress((void**)&qkv,  g_qkv);
    cudaGetSymbolAddress((void**)&vT,   g_vT);
    cudaGetSymbolAddress((void**)&attn, g_attn);
    cudaGetSymbolAddress((void**)&x2,   g_x2);
    cudaGetSymbolAddress((void**)&hb,   g_hbuf);
    cudaGetSymbolAddress((void**)&wr,   g_wr);
    cudaGetSymbolAddress((void**)&bqkv, g_bqkv);

    constexpr int M1 = 1024 * 1024;
    __half* wqkvr = wr;
    __half* wor = wr + 3 * M1;
    __half* w1r = wr + 4 * M1;
    __half* w2r = wr + 8 * M1;

    constexpr int SMG  = 3 * 256 * 128;   // 98304  (BM=128)
    constexpr int SMGB = 3 * 384 * 128;   // 147456 (BM=256)
    cudaFuncSetAttribute(mma_gemm<128, false, false, false, 2>,
                         cudaFuncAttributeMaxDynamicSharedMemorySize, SMG);
    cudaFuncSetAttribute(mma_gemm<256, false, true,  true,  1>,
                         cudaFuncAttributeMaxDynamicSharedMemorySize, SMGB);
    cudaFuncSetAttribute(mma_gemm<256, true,  true,  false, 1>,
                         cudaFuncAttributeMaxDynamicSharedMemorySize, SMGB);
    cudaFuncSetAttribute(mma_gemm<256, false, false, false, 1>,
                         cudaFuncAttributeMaxDynamicSharedMemorySize, SMGB);
    cudaFuncSetAttribute(flash_attn_kernel, cudaFuncAttributeMaxDynamicSharedMemorySize,
                         fa::SMEM_BYTES);

    // 0. setup: weight conversion + bias concat + LN1 (one launch)
    setup_kernel<<<16396, 256>>>(wq, wk, wv, wo, w1, w2, bq, bk_, bv,
                                 wr, bqkv, x, ln, a1, be1);

    // 1. fused QKV projection (256-row tile); V-column blocks write vT transposed
    mma_gemm<256, false, true, true, 1>
        <<<dim3(QKV_LD / 128, ROWS_ / 256), 512, SMGB>>>(
            ln, wqkvr, bqkv, nullptr, qkv, vT, D_, D_, D_, QKV_LD, 1.0f);

    // 2. fused flash attention -> attn (half); 128-row q tiles
    flash_attn_kernel<<<dim3(S_ / 128, B_ * H_), 256, fa::SMEM_BYTES>>>(
        qkv, qkv + D_, vT, msk, attn);

    // 3. x2 = attn @ wo^T + bo + x (fp32 out + residual; DRAM-bound, 128 tile)
    mma_gemm<128, false, false, false, 2>
        <<<dim3(D_ / 128, ROWS_ / 128), 256, SMG>>>(
            attn, wor, bo, x, x2, nullptr, D_, D_, D_, D_, 1.0f);

    // 4. LN2 (half output)
    layernorm_kernel<<<ROWS_, 256>>>(x2, ln, a2, be2);

    // 5. h = relu(ln @ w1^T + b1) (256-row tile, half out)
    mma_gemm<256, true, true, false, 1>
        <<<dim3(DFF_ / 128, ROWS_ / 256), 512, SMGB>>>(
            ln, w1r, b1, nullptr, hb, nullptr, D_, D_, D_, DFF_, 1.0f);

    // 6. out = h @ w2^T + b2 + x2 (256-row tile, fp32 out + residual)
    mma_gemm<256, false, false, false, 1>
        <<<dim3(D_ / 128, ROWS_ / 256), 512, SMGB>>>(
            hb, w2r, b2, x2, out, nullptr, DFF_, DFF_, DFF_, D_, 1.0f);
}

// round 15
// speedup vs baseline: 1.0490x; 1.0490x over previous
#include <cuda_runtime.h>
#include <cuda_fp16.h>
#include <cstdint>

// ---------------------------------------------------------------------------
// EncoderBlock: pre-norm transformer block.  (R13 configuration — best: 473us)
// GEMMs + flash attention via mma.sync m16n8k16 fp16 (fp32 accumulate).
// GEMM: 128x128x64 tile, 8 warps, 2 CTAs/SM (empirical optimum).
// FA: FA2 register-P. QKV epilogue writes V transposed. Merged setup kernel.
// B=2, S=2048, D=1024, H=16, DK=64, DFF=4096
// ---------------------------------------------------------------------------

namespace {
constexpr int B_ = 2, S_ = 2048, D_ = 1024, H_ = 16, DK_ = 64, DFF_ = 4096;
constexpr int ROWS_ = B_ * S_;            // 4096
constexpr int QKV_LD = 3 * D_;            // 3072
constexpr float EPS_ = 1e-6f;
constexpr float SFT_SC = 0.125f * 1.44269504088896f;   // (1/8)*log2(e)
}

// Scratch (allocation-free: __device__ globals)
__device__ __align__(16) __half g_ln[ROWS_ * D_];
__device__ __align__(16) __half g_qkv[ROWS_ * QKV_LD];
__device__ __align__(16) __half g_vT[B_ * H_ * DK_ * S_];
__device__ __align__(16) __half g_attn[ROWS_ * D_];
__device__ __align__(16) float  g_x2[ROWS_ * D_];
__device__ __align__(16) __half g_hbuf[ROWS_ * DFF_];
__device__ __align__(16) __half g_wr[12 * 1024 * 1024];   // half weights (24MB)
__device__ __align__(16) float  g_bqkv[QKV_LD];

// ---------------------------------------------------------------------------
// PTX helpers
// ---------------------------------------------------------------------------
__device__ __forceinline__ uint32_t smem_u32(const void* p) {
    uint32_t a;
    asm("{ .reg .u64 t; cvta.to.shared.u64 t, %1; cvt.u32.u64 %0, t; }"
        : "=r"(a) : "l"(p));
    return a;
}

__device__ __forceinline__ void cp_async16(uint32_t s, const void* g) {
    asm volatile("cp.async.cg.shared.global [%0], [%1], 16;" :: "r"(s), "l"(g));
}
#define CP_COMMIT() asm volatile("cp.async.commit_group;" ::: "memory")
#define CP_WAIT(n)  asm volatile("cp.async.wait_group %0;" :: "n"(n) : "memory")

__device__ __forceinline__ void mma_f16(float* c, const uint32_t* a, const uint32_t* b) {
    asm volatile(
        "mma.sync.aligned.m16n8k16.row.col.f32.f16.f16.f32 "
        "{%0,%1,%2,%3}, {%4,%5,%6,%7}, {%8,%9}, {%0,%1,%2,%3};"
        : "+f"(c[0]), "+f"(c[1]), "+f"(c[2]), "+f"(c[3])
        : "r"(a[0]), "r"(a[1]), "r"(a[2]), "r"(a[3]), "r"(b[0]), "r"(b[1]));
}

__device__ __forceinline__ void ldsm_x4(uint32_t* r, uint32_t saddr) {
    asm volatile("ldmatrix.sync.aligned.m8n8.x4.shared.b16 {%0,%1,%2,%3}, [%4];"
                 : "=r"(r[0]), "=r"(r[1]), "=r"(r[2]), "=r"(r[3]) : "r"(saddr));
}

__device__ __forceinline__ uint32_t h2u(__half2 h) {
    return *reinterpret_cast<uint32_t*>(&h);
}

// ---------------------------------------------------------------------------
// Fused setup: weight fp32->fp16 + bias concat + LN1, one launch (1D grid).
// Blocks: [0,1024) wq | [1024,2048) wk | [2048,3072) wv | [3072,4096) wo |
//         [4096,8192) w1 | [8192,12288) w2 | [12288,12300) bias | rest LN1.
// ---------------------------------------------------------------------------
__global__ void setup_kernel(const float* __restrict__ wq, const float* __restrict__ wk,
                             const float* __restrict__ wv, const float* __restrict__ wo,
                             const float* __restrict__ w1, const float* __restrict__ w2,
                             const float* __restrict__ bq, const float* __restrict__ bk,
                             const float* __restrict__ bv,
                             __half* __restrict__ dst, float* __restrict__ bqkv,
                             const float* __restrict__ x, __half* __restrict__ ln,
                             const float* __restrict__ alpha,
                             const float* __restrict__ beta) {
    __shared__ float red_s[256];
    __shared__ float red_q[256];
    constexpr int M1 = 1024 * 1024;
    const int bid = blockIdx.x;
    const int tid = threadIdx.x;

    if (bid < 12288) {                      // weight conversion
        const float* src;
        size_t off;
        int rb;
        if (bid < 1024)      { src = wq; off = 0;              rb = bid; }
        else if (bid < 2048) { src = wk; off = (size_t)M1;     rb = bid - 1024; }
        else if (bid < 3072) { src = wv; off = 2 * (size_t)M1; rb = bid - 2048; }
        else if (bid < 4096) { src = wo; off = 3 * (size_t)M1; rb = bid - 3072; }
        else if (bid < 8192) { src = w1; off = 4 * (size_t)M1; rb = bid - 4096; }
        else                 { src = w2; off = 8 * (size_t)M1; rb = bid - 8192; }
        const int i = rb * 256 + tid;
        float4 v = reinterpret_cast<const float4*>(src)[i];
        __half2* d = reinterpret_cast<__half2*>(dst + off) + i * 2;
        d[0] = __floats2half2_rn(v.x, v.y);
        d[1] = __floats2half2_rn(v.z, v.w);
        return;
    }
    if (bid < 12300) {                      // bias concat
        const int i = (bid - 12288) * 256 + tid;
        if (i < 1024) bqkv[i] = bq[i];
        else if (i < 2048) bqkv[i] = bk[i - 1024];
        else bqkv[i] = bv[i - 2048];
        return;
    }
    // LN1: one block per row
    const int row = bid - 12300;
    const size_t off = (size_t)row * D_;
    float4 r = reinterpret_cast<const float4*>(x + off)[tid];
    float s = r.x + r.y + r.z + r.w;
    float q = r.x * r.x + r.y * r.y + r.z * r.z + r.w * r.w;
    red_s[tid] = s;
    red_q[tid] = q;
    __syncthreads();
    #pragma unroll
    for (int st = 128; st > 0; st >>= 1) {
        if (tid < st) { red_s[tid] += red_s[tid + st]; red_q[tid] += red_q[tid + st]; }
        __syncthreads();
    }
    const float mean = red_s[0] * (1.0f / D_);
    float var = (red_q[0] - (float)D_ * mean * mean) * (1.0f / (float)(D_ - 1));
    var = fmaxf(var, 0.0f);
    const float sc = alpha[0] / (sqrtf(var) + EPS_);
    const float sh = beta[0];
    __half2* yo = reinterpret_cast<__half2*>(ln + off) + tid * 2;
    yo[0] = __floats2half2_rn((r.x - mean) * sc + sh, (r.y - mean) * sc + sh);
    yo[1] = __floats2half2_rn((r.z - mean) * sc + sh, (r.w - mean) * sc + sh);
}

// ---------------------------------------------------------------------------
// LayerNorm (exact fp32 math): unbiased std (ddof=1), scalar alpha/beta.
// ---------------------------------------------------------------------------
__global__ void layernorm_kernel(const float* __restrict__ x, __half* __restrict__ y,
                                 const float* __restrict__ alpha,
                                 const float* __restrict__ beta) {
    __shared__ float red_s[256];
    __shared__ float red_q[256];
    const int tid = threadIdx.x;
    const size_t off = (size_t)blockIdx.x * D_;
    float4 r = reinterpret_cast<const float4*>(x + off)[tid];
    float s = r.x + r.y + r.z + r.w;
    float q = r.x * r.x + r.y * r.y + r.z * r.z + r.w * r.w;
    red_s[tid] = s;
    red_q[tid] = q;
    __syncthreads();
    #pragma unroll
    for (int st = 128; st > 0; st >>= 1) {
        if (tid < st) { red_s[tid] += red_s[tid + st]; red_q[tid] += red_q[tid + st]; }
        __syncthreads();
    }
    const float mean = red_s[0] * (1.0f / D_);
    float var = (red_q[0] - (float)D_ * mean * mean) * (1.0f / (float)(D_ - 1));
    var = fmaxf(var, 0.0f);
    const float sc = alpha[0] / (sqrtf(var) + EPS_);
    const float sh = beta[0];
    __half2* yo = reinterpret_cast<__half2*>(y + off) + tid * 2;
    yo[0] = __floats2half2_rn((r.x - mean) * sc + sh, (r.y - mean) * sc + sh);
    yo[1] = __floats2half2_rn((r.z - mean) * sc + sh, (r.w - mean) * sc + sh);
}

// ---------------------------------------------------------------------------
// fp16 tensor-core GEMM (NT): 128x128x64, 8 warps, 3-stage cp.async, 2 CTAs/SM.
// VTRANS: blocks with blockIdx.x >= 16 (QKV V-columns) write their tile
// TRANSPOSED to vt (head-major vT layout) via an SMEM-staged transpose.
// ---------------------------------------------------------------------------
template <bool RELU, bool OUTHALF, bool VTRANS>
__global__ void __launch_bounds__(256, 2)
mma_gemm(const __half* __restrict__ A, const __half* __restrict__ Bm,
         const float* __restrict__ bias, const float* __restrict__ res,
         void* __restrict__ Cv, __half* __restrict__ vt,
         int K, int lda, int ldb, int ldc, float scale) {
    constexpr int STGB = 256 * 128;
    constexpr int BOFFB = 128 * 128;

    extern __shared__ char smc[];

    const int tid = threadIdx.x;
    const int wid = tid >> 5;
    const int lane = tid & 31;
    const int grp = lane >> 2;
    const int tid4 = lane & 3;
    const int wm0 = (wid >> 2) * 64;
    const int wn0 = (wid & 3) * 32;

    const int l7 = lane & 7;
    const int aRB = ((lane >> 3) & 1) * 8 + l7;
    const int aCB = lane >> 4;
    const int bRB = ((lane >> 4) & 1) * 8 + l7;
    const int bCB = (lane >> 3) & 1;

    const int row0 = blockIdx.y * 128;
    const int col0 = blockIdx.x * 128;

    int aGo[4]; uint32_t aSm[4];
    #pragma unroll
    for (int l = 0; l < 4; l++) {
        const int idx4 = tid + l * 256;
        const int r = idx4 >> 3, ch = idx4 & 7;
        aGo[l] = (row0 + r) * lda + ch * 8;
        aSm[l] = (uint32_t)(r * 128 + ((ch ^ (r & 7)) << 4));
    }
    int bGo[4]; uint32_t bSm[4];
    #pragma unroll
    for (int l = 0; l < 4; l++) {
        const int idx4 = tid + l * 256;
        const int r = idx4 >> 3, ch = idx4 & 7;
        bGo[l] = (col0 + r) * ldb + ch * 8;
        bSm[l] = (uint32_t)(BOFFB + r * 128 + ((ch ^ (r & 7)) << 4));
    }
    const uint32_t smBase = smem_u32(smc);

    float acc[4][4][4];
    #pragma unroll
    for (int i = 0; i < 4; i++)
        #pragma unroll
        for (int j = 0; j < 4; j++)
            #pragma unroll
            for (int e = 0; e < 4; e++) acc[i][j][e] = 0.0f;

    const int nch = K / 64;

    #pragma unroll
    for (int s = 0; s < 2; s++) {
        const uint32_t sb = smBase + (uint32_t)(s % 3) * STGB;
        const int k0 = s * 64;
        #pragma unroll
        for (int l = 0; l < 4; l++) cp_async16(sb + aSm[l], A + aGo[l] + k0);
        #pragma unroll
        for (int l = 0; l < 4; l++) cp_async16(sb + bSm[l], Bm + bGo[l] + k0);
        CP_COMMIT();
    }

    for (int ci = 0; ci < nch; ci++) {
        if (ci + 2 < nch) { CP_WAIT(1); } else { CP_WAIT(0); }
        __syncthreads();
        if (ci + 2 < nch) {
            const int s = ci + 2;
            const uint32_t sb = smBase + (uint32_t)(s % 3) * STGB;
            const int k0 = s * 64;
            #pragma unroll
            for (int l = 0; l < 4; l++) cp_async16(sb + aSm[l], A + aGo[l] + k0);
            #pragma unroll
            for (int l = 0; l < 4; l++) cp_async16(sb + bSm[l], Bm + bGo[l] + k0);
            CP_COMMIT();
        }

        const uint32_t suA = smBase + (uint32_t)(ci % 3) * STGB;
        const uint32_t suB = suA + (uint32_t)BOFFB;

        #pragma unroll
        for (int ks = 0; ks < 4; ks++) {
            const uint32_t aSw = (uint32_t)(((2 * ks + aCB) ^ l7) << 4);
            const uint32_t bSw = (uint32_t)(((2 * ks + bCB) ^ l7) << 4);
            uint32_t a[4][4];
            #pragma unroll
            for (int ma = 0; ma < 4; ma++)
                ldsm_x4(a[ma], suA + (uint32_t)(wm0 + ma * 16 + aRB) * 128u + aSw);
            uint32_t bq[2][4];
            #pragma unroll
            for (int np = 0; np < 2; np++)
                ldsm_x4(bq[np], suB + (uint32_t)(wn0 + np * 16 + bRB) * 128u + bSw);
            #pragma unroll
            for (int ma = 0; ma < 4; ma++)
                #pragma unroll
                for (int na = 0; na < 4; na++)
                    mma_f16(acc[ma][na], a[ma], &bq[na >> 1][(na & 1) * 2]);
        }
    }

    if (VTRANS && blockIdx.x >= 16) {
        // --- transposed epilogue: stage half tile sT[feature][s-row] and
        //     write coalesced rows of vT[(b*16+h)*64+n][s] ---
        constexpr int TP = 136;               // padded halfs per feature row
        __half* sT = reinterpret_cast<__half*>(smc);
        __syncthreads();                      // all MMA smem reads done
        #pragma unroll
        for (int ma = 0; ma < 4; ma++) {
            const int rr = wm0 + ma * 16 + grp;
            #pragma unroll
            for (int na = 0; na < 4; na++) {
                const int cc = wn0 + na * 8 + tid4 * 2;
                float2 v0, v1;
                v0.x = acc[ma][na][0]; v0.y = acc[ma][na][1];
                v1.x = acc[ma][na][2]; v1.y = acc[ma][na][3];
                if (bias) {
                    const float2 bv = *reinterpret_cast<const float2*>(bias + col0 + cc);
                    v0.x += bv.x; v0.y += bv.y; v1.x += bv.x; v1.y += bv.y;
                }
                sT[cc * TP + rr]           = __float2half_rn(v0.x);
                sT[(cc + 1) * TP + rr]     = __float2half_rn(v0.y);
                sT[cc * TP + rr + 8]       = __float2half_rn(v1.x);
                sT[(cc + 1) * TP + rr + 8] = __float2half_rn(v1.y);
            }
        }
        __syncthreads();
        const int b = row0 >> 11;             // row0 / 2048
        const int s0 = row0 & 2047;
        #pragma unroll
        for (int l = 0; l < 8; l++) {
            const int idx = tid + l * 256;
            const int c = idx >> 4, su = idx & 15;
            const int f = col0 - 2048 + c;
            const int h = f >> 6, n = f & 63;
            const uint4 val = *reinterpret_cast<const uint4*>(&sT[c * TP + su * 8]);
            *reinterpret_cast<uint4*>(
                vt + ((size_t)((b * 16 + h) * 64 + n)) * 2048 + s0 + su * 8) = val;
        }
        return;
    }

    #pragma unroll
    for (int ma = 0; ma < 4; ma++) {
        const int rr = row0 + wm0 + ma * 16 + grp;
        #pragma unroll
        for (int na = 0; na < 4; na++) {
            const int cc = col0 + wn0 + na * 8 + tid4 * 2;
            float2 v0, v1;
            v0.x = acc[ma][na][0] * scale; v0.y = acc[ma][na][1] * scale;
            v1.x = acc[ma][na][2] * scale; v1.y = acc[ma][na][3] * scale;
            if (bias) {
                const float2 bv = *reinterpret_cast<const float2*>(bias + cc);
                v0.x += bv.x; v0.y += bv.y; v1.x += bv.x; v1.y += bv.y;
            }
            if (RELU) {
                v0.x = fmaxf(v0.x, 0.0f); v0.y = fmaxf(v0.y, 0.0f);
                v1.x = fmaxf(v1.x, 0.0f); v1.y = fmaxf(v1.y, 0.0f);
            }
            const long long o0 = (long long)rr * ldc + cc;
            const long long o1 = (long long)(rr + 8) * ldc + cc;
            if (OUTHALF) {
                __half* C = reinterpret_cast<__half*>(Cv);
                *reinterpret_cast<__half2*>(C + o0) = __floats2half2_rn(v0.x, v0.y);
                *reinterpret_cast<__half2*>(C + o1) = __floats2half2_rn(v1.x, v1.y);
            } else {
                float* C = reinterpret_cast<float*>(Cv);
                if (res) {
                    const float2 r0 = *reinterpret_cast<const float2*>(res + o0);
                    const float2 r1 = *reinterpret_cast<const float2*>(res + o1);
                    v0.x += r0.x; v0.y += r0.y; v1.x += r1.x; v1.y += r1.y;
                }
                *reinterpret_cast<float2*>(C + o0) = v0;
                *reinterpret_cast<float2*>(C + o1) = v1;
            }
        }
    }
}

// ---------------------------------------------------------------------------
// Fused flash attention, FA2 register-P (proven R12 config).
// ---------------------------------------------------------------------------
namespace fa {
constexpr int oQ = 0, oK = 16384, oVT = 49152;
constexpr int SMEM_BYTES = 81920;
constexpr int NIT = S_ / 128;                  // 16
}

__global__ void __launch_bounds__(256, 2)
flash_attn_kernel(const __half* __restrict__ q, const __half* __restrict__ k,
                  const __half* __restrict__ vT, const int* __restrict__ mask,
                  __half* __restrict__ attn) {
    using namespace fa;
    extern __shared__ char smc[];
    const uint32_t smb = smem_u32(smc);

    const int tid = threadIdx.x, wid = tid >> 5, lane = tid & 31;
    const int grp = lane >> 2, tid4 = lane & 3;
    const int wm = wid * 16;

    const int l7 = lane & 7;
    const int aRB = ((lane >> 3) & 1) * 8 + l7;
    const int aCB = lane >> 4;
    const int bRB = ((lane >> 4) & 1) * 8 + l7;
    const int bCB = (lane >> 3) & 1;

    const int qt = blockIdx.x;
    const int bh = blockIdx.y;
    const int b = bh >> 4, hh = bh & 15;
    const int q0 = qt * 128;
    const __half* Qg = q + ((size_t)(b * S_ + q0)) * QKV_LD + hh * 64;
    const __half* Kg = k + ((size_t)(b * S_)) * QKV_LD + hh * 64;
    const __half* Vg = vT + (size_t)bh * 64 * S_;
    const int* maskb = mask + b * S_;

    #pragma unroll
    for (int l = 0; l < 4; l++) {
        const int i4 = tid + l * 256;
        const int r = i4 >> 3, c = i4 & 7;
        cp_async16(smb + (uint32_t)(oQ + r * 128 + ((c ^ (r & 7)) << 4)),
                   Qg + (size_t)r * QKV_LD + c * 8);
    }
    #pragma unroll
    for (int l = 0; l < 4; l++) {
        const int i4 = tid + l * 256;
        const int r = i4 >> 3, c = i4 & 7;
        cp_async16(smb + (uint32_t)(oK + r * 128 + ((c ^ (r & 7)) << 4)),
                   Kg + (size_t)r * QKV_LD + c * 8);
    }
    CP_COMMIT();
    #pragma unroll
    for (int l = 0; l < 4; l++) {
        const int i4 = tid + l * 256;
        const int r = i4 >> 4, c = i4 & 15;
        cp_async16(smb + (uint32_t)(oVT + r * 256 + ((c ^ (r & 7)) << 4)),
                   Vg + (size_t)r * S_ + c * 8);
    }
    CP_COMMIT();

    float acc_o[8][4];
    #pragma unroll
    for (int j = 0; j < 8; j++)
        #pragma unroll
        for (int e = 0; e < 4; e++) acc_o[j][e] = 0.0f;

    float m0 = -3.0e38f, m1 = -3.0e38f;
    float l0 = 0.0f, l1 = 0.0f;

    for (int it = 0; it < NIT; ++it) {
        const int kv0 = it * 128;
        const uint32_t kCur = smb + (uint32_t)(oK + (it & 1) * 16384);
        const uint32_t vCur = smb + (uint32_t)(oVT + (it & 1) * 16384);

        CP_WAIT(1);
        __syncthreads();            // barrier 1

        if (it + 1 < NIT) {
            const uint32_t kNxt = smb + (uint32_t)(oK + ((it + 1) & 1) * 16384);
            const __half* Kn = Kg + (size_t)(kv0 + 128) * QKV_LD;
            #pragma unroll
            for (int l = 0; l < 4; l++) {
                const int i4 = tid + l * 256;
                const int r = i4 >> 3, c = i4 & 7;
                cp_async16(kNxt + (uint32_t)(r * 128 + ((c ^ (r & 7)) << 4)),
                           Kn + (size_t)r * QKV_LD + c * 8);
            }
            CP_COMMIT();
        }

        // ---- S = Q K^T : warp = 16 rows x 128 kv ----
        float acc_s[16][4];
        #pragma unroll
        for (int j = 0; j < 16; j++)
            #pragma unroll
            for (int e = 0; e < 4; e++) acc_s[j][e] = 0.0f;

        #pragma unroll
        for (int ks = 0; ks < 4; ks++) {
            const uint32_t aSw = (uint32_t)(((2 * ks + aCB) ^ l7) << 4);
            const uint32_t bSw = (uint32_t)(((2 * ks + bCB) ^ l7) << 4);
            uint32_t a[4];
            ldsm_x4(a, smb + (uint32_t)(oQ + (wm + aRB) * 128) + aSw);
            #pragma unroll
            for (int h = 0; h < 2; h++) {
                uint32_t bq[4][4];
                #pragma unroll
                for (int np = 0; np < 4; np++)
                    ldsm_x4(bq[np],
                            kCur + (uint32_t)((h * 64 + np * 16 + bRB) * 128) + bSw);
                #pragma unroll
                for (int j = 0; j < 8; j++)
                    mma_f16(acc_s[h * 8 + j], a, &bq[j >> 1][(j & 1) * 2]);
            }
        }

        // ---- mask + log2 scale + in-warp row max ----
        float p0 = -3.0e38f, p1 = -3.0e38f;
        #pragma unroll
        for (int na = 0; na < 16; na++) {
            const int cg = kv0 + na * 8 + tid4 * 2;
            const int2 mm = *reinterpret_cast<const int2*>(maskb + cg);
            float* s = acc_s[na];
            s[0] = mm.x ? s[0] * SFT_SC : -1e9f;
            s[1] = mm.y ? s[1] * SFT_SC : -1e9f;
            s[2] = mm.x ? s[2] * SFT_SC : -1e9f;
            s[3] = mm.y ? s[3] * SFT_SC : -1e9f;
            p0 = fmaxf(p0, fmaxf(s[0], s[1]));
            p1 = fmaxf(p1, fmaxf(s[2], s[3]));
        }
        #pragma unroll
        for (int d2 = 1; d2 < 4; d2 <<= 1) {
            p0 = fmaxf(p0, __shfl_xor_sync(0xffffffffu, p0, d2));
            p1 = fmaxf(p1, __shfl_xor_sync(0xffffffffu, p1, d2));
        }
        const float mn0 = fmaxf(m0, p0);
        const float mn1 = fmaxf(m1, p1);
        const float c0 = exp2f(m0 - mn0);
        const float c1 = exp2f(m1 - mn1);
        m0 = mn0; m1 = mn1;

        // ---- exp2, convert P to half2 register fragments, row sums ----
        uint32_t phl[16], phh[16];
        float s0sum = 0.0f, s1sum = 0.0f;
        #pragma unroll
        for (int na = 0; na < 16; na++) {
            float* s = acc_s[na];
            s[0] = exp2f(s[0] - mn0);
            s[1] = exp2f(s[1] - mn0);
            s[2] = exp2f(s[2] - mn1);
            s[3] = exp2f(s[3] - mn1);
            s0sum += s[0] + s[1];
            s1sum += s[2] + s[3];
            phl[na] = h2u(__floats2half2_rn(s[0], s[1]));
            phh[na] = h2u(__floats2half2_rn(s[2], s[3]));
        }
        #pragma unroll
        for (int d2 = 1; d2 < 4; d2 <<= 1) {
            s0sum += __shfl_xor_sync(0xffffffffu, s0sum, d2);
            s1sum += __shfl_xor_sync(0xffffffffu, s1sum, d2);
        }
        l0 = l0 * c0 + s0sum;
        l1 = l1 * c1 + s1sum;

        CP_WAIT(1);
        __syncthreads();            // barrier 2: VT visible

        if (it + 1 < NIT) {
            const uint32_t vNxt = smb + (uint32_t)(oVT + ((it + 1) & 1) * 16384);
            const __half* Vn = Vg + kv0 + 128;
            #pragma unroll
            for (int l = 0; l < 4; l++) {
                const int i4 = tid + l * 256;
                const int r = i4 >> 4, c = i4 & 15;
                cp_async16(vNxt + (uint32_t)(r * 256 + ((c ^ (r & 7)) << 4)),
                           Vn + (size_t)r * S_ + c * 8);
            }
            CP_COMMIT();
        }

        // ---- correction + PV ----
        #pragma unroll
        for (int na = 0; na < 8; na++) {
            acc_o[na][0] *= c0; acc_o[na][1] *= c0;
            acc_o[na][2] *= c1; acc_o[na][3] *= c1;
        }
        #pragma unroll
        for (int ks = 0; ks < 8; ks++) {
            uint32_t a[4] = { phl[2 * ks], phh[2 * ks], phl[2 * ks + 1], phh[2 * ks + 1] };
            const uint32_t bSw = (uint32_t)(((2 * ks + bCB) ^ l7) << 4);
            uint32_t bq[4][4];
            #pragma unroll
            for (int np = 0; np < 4; np++)
                ldsm_x4(bq[np], vCur + (uint32_t)((np * 16 + bRB) * 256) + bSw);
            #pragma unroll
            for (int nd = 0; nd < 8; nd++)
                mma_f16(acc_o[nd], a, &bq[nd >> 1][(nd & 1) * 2]);
        }
    }

    // ---- normalize and store ----
    const float inv0 = 1.0f / l0;
    const float inv1 = 1.0f / l1;
    const int rA = wm + grp;
    #pragma unroll
    for (int nd = 0; nd < 8; nd++) {
        const int cd = nd * 8 + tid4 * 2;
        const size_t o0 = ((size_t)(b * S_ + q0 + rA)) * D_ + hh * 64 + cd;
        const size_t o1 = o0 + (size_t)8 * D_;
        *reinterpret_cast<__half2*>(attn + o0) =
            __floats2half2_rn(acc_o[nd][0] * inv0, acc_o[nd][1] * inv0);
        *reinterpret_cast<__half2*>(attn + o1) =
            __floats2half2_rn(acc_o[nd][2] * inv1, acc_o[nd][3] * inv1);
    }
}

// ---------------------------------------------------------------------------
// kernel_launch
// ---------------------------------------------------------------------------
extern "C" void kernel_launch(void* const* d_in, const int* in_sizes, int n_in,
                              void* d_out, int out_size) {
    const float* x    = (const float*)d_in[0];
    const int*   msk  = (const int*)  d_in[1];
    const float* wq   = (const float*)d_in[2];
    const float* bq   = (const float*)d_in[3];
    const float* wk   = (const float*)d_in[4];
    const float* bk_  = (const float*)d_in[5];
    const float* wv   = (const float*)d_in[6];
    const float* bv   = (const float*)d_in[7];
    const float* wo   = (const float*)d_in[8];
    const float* bo   = (const float*)d_in[9];
    const float* w1   = (const float*)d_in[10];
    const float* b1   = (const float*)d_in[11];
    const float* w2   = (const float*)d_in[12];
    const float* b2   = (const float*)d_in[13];
    const float* a1   = (const float*)d_in[14];
    const float* be1  = (const float*)d_in[15];
    const float* a2   = (const float*)d_in[16];
    const float* be2  = (const float*)d_in[17];
    float* out = (float*)d_out;

    __half *ln, *qkv, *vT, *attn, *hb, *wr;
    float *x2, *bqkv;
    cudaGetSymbolAddress((void**)&ln,   g_ln);
    cudaGetSymbolAddress((void**)&qkv,  g_qkv);
    cudaGetSymbolAddress((void**)&vT,   g_vT);
    cudaGetSymbolAddress((void**)&attn, g_attn);
    cudaGetSymbolAddress((void**)&x2,   g_x2);
    cudaGetSymbolAddress((void**)&hb,   g_hbuf);
    cudaGetSymbolAddress((void**)&wr,   g_wr);
    cudaGetSymbolAddress((void**)&bqkv, g_bqkv);

    constexpr int M1 = 1024 * 1024;
    __half* wqkvr = wr;
    __half* wor = wr + 3 * M1;
    __half* w1r = wr + 4 * M1;
    __half* w2r = wr + 8 * M1;

    constexpr int SMG = 3 * 256 * 128;
    cudaFuncSetAttribute(mma_gemm<false, false, false>, cudaFuncAttributeMaxDynamicSharedMemorySize, SMG);
    cudaFuncSetAttribute(mma_gemm<false, true,  true>,  cudaFuncAttributeMaxDynamicSharedMemorySize, SMG);
    cudaFuncSetAttribute(mma_gemm<true,  true,  false>, cudaFuncAttributeMaxDynamicSharedMemorySize, SMG);
    cudaFuncSetAttribute(flash_attn_kernel, cudaFuncAttributeMaxDynamicSharedMemorySize,
                         fa::SMEM_BYTES);

    // 0. setup: weight conversion + bias concat + LN1 (one launch)
    setup_kernel<<<16396, 256>>>(wq, wk, wv, wo, w1, w2, bq, bk_, bv,
                                 wr, bqkv, x, ln, a1, be1);

    // 1. fused QKV projection; V-column blocks write vT transposed
    mma_gemm<false, true, true><<<dim3(QKV_LD / 128, ROWS_ / 128), 256, SMG>>>(
        ln, wqkvr, bqkv, nullptr, qkv, vT, D_, D_, D_, QKV_LD, 1.0f);

    // 2. fused flash attention -> attn (half); 128-row q tiles
    flash_attn_kernel<<<dim3(S_ / 128, B_ * H_), 256, fa::SMEM_BYTES>>>(
        qkv, qkv + D_, vT, msk, attn);

    // 3. x2 = attn @ wo^T + bo + x (fp32 out + residual)
    mma_gemm<false, false, false><<<dim3(D_ / 128, ROWS_ / 128), 256, SMG>>>(
        attn, wor, bo, x, x2, nullptr, D_, D_, D_, D_, 1.0f);

    // 4. LN2 (half output)
    layernorm_kernel<<<ROWS_, 256>>>(x2, ln, a2, be2);

    // 5. h = relu(ln @ w1^T + b1) (half out)
    mma_gemm<true, true, false><<<dim3(DFF_ / 128, ROWS_ / 128), 256, SMG>>>(
        ln, w1r, b1, nullptr, hb, nullptr, D_, D_, D_, DFF_, 1.0f);

    // 6. out = h @ w2^T + b2 + x2 (fp32 out + residual)
    mma_gemm<false, false, false><<<dim3(D_ / 128, ROWS_ / 128), 256, SMG>>>(
        hb, w2r, b2, x2, out, nullptr, DFF_, DFF_, DFF_, D_, 1.0f);
}